// round 8
// baseline (speedup 1.0000x reference)
#include <cuda_runtime.h>
#include <cstdint>

#define BATCH 4
#define NPTS  4096
#define FIN   64
#define FOUT  64
#define KNN   20
#define TOTAL (BATCH * NPTS)   // 16384 points

// ---------------- scratch (static device memory; no allocations) ----------------
__device__ float g_key[(size_t)TOTAL * NPTS];   // 268 MB ranking keys
__device__ float g_u[TOTAL * FOUT];             // (W1-W2)x + b
__device__ float g_v[TOTAL * FOUT];             // W2 x
__device__ float g_xs[TOTAL];                   // squared norms
__device__ int   g_idx[TOTAL * KNN];            // knn indices (local to batch)

// ---------------- kernel A: per-point transform ----------------
__global__ void transform_kernel(const float* __restrict__ x,
                                 const float* __restrict__ W,
                                 const float* __restrict__ bias) {
    __shared__ float Ws[FOUT * 2 * FIN];
    __shared__ float bs[FOUT];
    int t = threadIdx.x;
    for (int i = t; i < FOUT * 2 * FIN; i += blockDim.x) Ws[i] = W[i];
    if (t < FOUT) bs[t] = bias[t];
    __syncthreads();

    int p = blockIdx.x * blockDim.x + t;
    float xr[FIN];
    const float4* xp = (const float4*)(x + (size_t)p * FIN);
#pragma unroll
    for (int q = 0; q < FIN / 4; q++) {
        float4 v4 = xp[q];
        xr[4*q+0] = v4.x; xr[4*q+1] = v4.y; xr[4*q+2] = v4.z; xr[4*q+3] = v4.w;
    }
    float s = 0.f;
#pragma unroll
    for (int c = 0; c < FIN; c++) s += xr[c] * xr[c];
    g_xs[p] = s;

    for (int o = 0; o < FOUT; o++) {
        float a1 = 0.f, a2 = 0.f;
        const float* wrow = &Ws[o * 2 * FIN];
#pragma unroll
        for (int c = 0; c < FIN; c++) {
            a1 += xr[c] * wrow[c];
            a2 += xr[c] * wrow[FIN + c];
        }
        g_u[p * FOUT + o] = a1 - a2 + bs[o];
        g_v[p * FOUT + o] = a2;
    }
}

// ---------------- kernel B: symmetric Gram + ranking keys ----------------
// Row-major smem tiles (stride 68: 64 data + 4 pad), f4-blocked micro-kernel.
// Tile fill: fully contiguous float4 stores (zero conflicts).
// A reads: warp-broadcast (lanes 0-15 share tr). B reads: bank stride 4 -> none.
#define TILE 128
#define RSTR 68
#define DIST_SMEM (2 * TILE * RSTR * 4)   // 69632 bytes

__global__ __launch_bounds__(256, 1) void dist_kernel(const float* __restrict__ x, int b) {
    extern __shared__ float sm[];
    float* As = sm;
    float* Bs = sm + TILE * RSTR;

    // map linear id -> upper-triangular (by, bx), bx >= by, 32x32 tile grid
    int id = blockIdx.x;
    int by = 0, rem = id;
    while (rem >= 32 - by) { rem -= 32 - by; by++; }
    int bx = by + rem;

    const float* X = x + (size_t)b * NPTS * FIN;
    int row0 = by * TILE, col0 = bx * TILE;
    int t  = threadIdx.x;
    int tr = t >> 4, tc = t & 15;          // 16 x 16 threads, 8x8 micro-tile

    // fill both tiles row-major (8 float4 iters each)
    for (int q = t; q < TILE * 16; q += 256) {
        int r  = q >> 4;
        int f4 = q & 15;
        *(float4*)&As[r * RSTR + f4 * 4] =
            *(const float4*)(X + (size_t)(row0 + r) * FIN + f4 * 4);
        *(float4*)&Bs[r * RSTR + f4 * 4] =
            *(const float4*)(X + (size_t)(col0 + r) * FIN + f4 * 4);
    }
    __syncthreads();

    float acc[8][8];
#pragma unroll
    for (int i = 0; i < 8; i++)
#pragma unroll
        for (int j = 0; j < 8; j++) acc[i][j] = 0.f;

    const float* Ab = As + (tr * 8) * RSTR;
    const float* Bb = Bs + (tc * 8) * RSTR;
#pragma unroll 4
    for (int f4 = 0; f4 < 16; f4++) {
        float4 av[8], bv[8];
#pragma unroll
        for (int i = 0; i < 8; i++) av[i] = *(const float4*)&Ab[i * RSTR + f4 * 4];
#pragma unroll
        for (int j = 0; j < 8; j++) bv[j] = *(const float4*)&Bb[j * RSTR + f4 * 4];
#pragma unroll
        for (int i = 0; i < 8; i++)
#pragma unroll
            for (int j = 0; j < 8; j++) {
                float a = fmaf(av[i].x, bv[j].x, acc[i][j]);
                a = fmaf(av[i].y, bv[j].y, a);
                a = fmaf(av[i].z, bv[j].z, a);
                a = fmaf(av[i].w, bv[j].w, a);
                acc[i][j] = a;
            }
    }

    float xsr[8], xsc[8];
#pragma unroll
    for (int i = 0; i < 8; i++) xsr[i] = g_xs[b * NPTS + row0 + tr * 8 + i];
#pragma unroll
    for (int j = 0; j < 8; j++) xsc[j] = g_xs[b * NPTS + col0 + tc * 8 + j];

    // direct block: key[row][col] = xs[col] - 2*acc   (streaming stores)
#pragma unroll
    for (int i = 0; i < 8; i++) {
        size_t base = (size_t)(b * NPTS + row0 + tr * 8 + i) * NPTS + col0 + tc * 8;
        float4 o0 = make_float4(xsc[0] - 2.f*acc[i][0], xsc[1] - 2.f*acc[i][1],
                                xsc[2] - 2.f*acc[i][2], xsc[3] - 2.f*acc[i][3]);
        float4 o1 = make_float4(xsc[4] - 2.f*acc[i][4], xsc[5] - 2.f*acc[i][5],
                                xsc[6] - 2.f*acc[i][6], xsc[7] - 2.f*acc[i][7]);
        __stcs((float4*)&g_key[base],     o0);
        __stcs((float4*)&g_key[base + 4], o1);
    }
    // mirrored block: key[col][row] = xs[row] - 2*acc
    if (bx != by) {
#pragma unroll
        for (int j = 0; j < 8; j++) {
            size_t base = (size_t)(b * NPTS + col0 + tc * 8 + j) * NPTS + row0 + tr * 8;
            float4 o0 = make_float4(xsr[0] - 2.f*acc[0][j], xsr[1] - 2.f*acc[1][j],
                                    xsr[2] - 2.f*acc[2][j], xsr[3] - 2.f*acc[3][j]);
            float4 o1 = make_float4(xsr[4] - 2.f*acc[4][j], xsr[5] - 2.f*acc[5][j],
                                    xsr[6] - 2.f*acc[6][j], xsr[7] - 2.f*acc[7][j]);
            __stcs((float4*)&g_key[base],     o0);
            __stcs((float4*)&g_key[base + 4], o1);
        }
    }
}

// ---------------- kernel C: radix top-20 selection (per batch) ----------------
__global__ __launch_bounds__(256) void select_kernel(int b) {
    int iLocal = blockIdx.x;
    int row = b * NPTS + iLocal;
    const float4* keys = (const float4*)(g_key + (size_t)row * NPTS);
    int t = threadIdx.x;

    unsigned v[16];
#pragma unroll
    for (int i2 = 0; i2 < 4; i2++) {
        int f4 = t + i2 * 256;
        float4 kv = __ldcs(&keys[f4]);
        float vv[4] = {kv.x, kv.y, kv.z, kv.w};
        int j0 = f4 * 4;
#pragma unroll
        for (int e = 0; e < 4; e++) {
            unsigned u = __float_as_uint(vv[e]);
            u = (u & 0x80000000u) ? ~u : (u | 0x80000000u);
            v[i2 * 4 + e] = (j0 + e == iLocal) ? 0xFFFFFFFFu : u;
        }
    }

    __shared__ int hist[256];
    __shared__ int sD, sCb, sNeed;
    __shared__ int cnt1, cntT, chosen;
    __shared__ int tieb[64];
    __shared__ int wred[8];

    unsigned prefix = 0, pmask = 0;
    if (t == 0) sNeed = KNN;

    for (int pass = 0; pass < 4; pass++) {
        int shift = 24 - 8 * pass;
        hist[t] = 0;
        __syncthreads();
#pragma unroll
        for (int q = 0; q < 16; q++) {
            bool ok = (v[q] & pmask) == prefix;
            unsigned act = __ballot_sync(0xffffffffu, ok);
            if (ok) {
                unsigned d = (v[q] >> shift) & 255u;
                unsigned m = __match_any_sync(act, d);
                if ((t & 31) == (__ffs(m) - 1))
                    atomicAdd(&hist[d], __popc(m));
            }
        }
        __syncthreads();
        if (t < 32) {
            int s[8], tot = 0, base = t * 8;
#pragma unroll
            for (int q2 = 0; q2 < 8; q2++) { s[q2] = hist[base + q2]; tot += s[q2]; }
            int inc = tot;
#pragma unroll
            for (int off = 1; off < 32; off <<= 1) {
                int o = __shfl_up_sync(0xffffffffu, inc, off);
                if (t >= off) inc += o;
            }
            int ex = inc - tot;
            int nd = sNeed;
            if (ex < nd && nd <= inc) {
                int run = ex;
#pragma unroll
                for (int q2 = 0; q2 < 8; q2++) {
                    if (nd <= run + s[q2]) { sD = base + q2; sCb = run; break; }
                    run += s[q2];
                }
            }
        }
        __syncthreads();
        prefix |= ((unsigned)sD) << shift;
        pmask  |= 0xFFu << shift;
        if (t == 0) sNeed -= sCb;
    }

    if (t == 0) { cnt1 = 0; cntT = 0; }
    __syncthreads();
    unsigned theta = prefix;
    int* outp = g_idx + row * KNN;
#pragma unroll
    for (int q = 0; q < 16; q++) {
        int j = (t + (q >> 2) * 256) * 4 + (q & 3);
        if (v[q] < theta)       { int s2 = atomicAdd(&cnt1, 1); outp[s2] = j; }
        else if (v[q] == theta) { int s2 = atomicAdd(&cntT, 1); if (s2 < 64) tieb[s2] = j; }
    }
    __syncthreads();
    int needF = sNeed;
    if (cntT <= 64) {
        if (t == 0) {
            int c1 = cnt1, nt = cntT;
            for (int s2 = 0; s2 < needF; s2++) {
                int bi = 0, bv = 0x7fffffff;
                for (int q = 0; q < nt; q++) if (tieb[q] < bv) { bv = tieb[q]; bi = q; }
                tieb[bi] = 0x7fffffff;
                outp[c1 + s2] = bv;
            }
        }
    } else {
        unsigned used = 0;
        for (int s2 = 0; s2 < needF; s2++) {
            int lm = 0x7fffffff;
#pragma unroll
            for (int q = 0; q < 16; q++) {
                int j = (t + (q >> 2) * 256) * 4 + (q & 3);
                if (v[q] == theta && !(used & (1u << q)) && j < lm) lm = j;
            }
            int r = lm;
#pragma unroll
            for (int off = 16; off; off >>= 1)
                r = min(r, __shfl_xor_sync(0xffffffffu, r, off));
            if ((t & 31) == 0) wred[t >> 5] = r;
            __syncthreads();
            if (t == 0) {
                int bm = 0x7fffffff;
                for (int w = 0; w < 8; w++) bm = min(bm, wred[w]);
                chosen = bm;
                outp[cnt1 + s2] = bm;
            }
            __syncthreads();
            int cj = chosen;
#pragma unroll
            for (int q = 0; q < 16; q++) {
                int j = (t + (q >> 2) * 256) * 4 + (q & 3);
                if (j == cj) used |= (1u << q);
            }
        }
    }
}

// ---------------- kernel D: gather-max epilogue ----------------
__global__ void gather_kernel(float* __restrict__ out) {
    int gid = blockIdx.x * blockDim.x + threadIdx.x;
    int p = gid >> 6;
    int o = gid & 63;
    int bbase = p & ~(NPTS - 1);
    const int* ip = g_idx + p * KNN;
    float m = -3.402823466e38f;
#pragma unroll
    for (int q = 0; q < KNN; q++) {
        int j = ip[q];
        m = fmaxf(m, g_v[(size_t)(bbase + j) * FOUT + o]);
    }
    out[gid] = g_u[gid] + m;
}

// ---------------- launch: per-batch dist/select pipeline, fork-join streams ----------------
extern "C" void kernel_launch(void* const* d_in, const int* in_sizes, int n_in,
                              void* d_out, int out_size) {
    const float* x    = (const float*)d_in[0];
    const float* W    = (const float*)d_in[1];
    const float* bias = (const float*)d_in[2];
    float* out = (float*)d_out;

    // one-time immutable resource setup (first call is the uncaptured
    // correctness run; per-call work is identical and deterministic)
    static cudaStream_t s_sel = nullptr;
    static cudaEvent_t  s_evD[BATCH];
    static cudaEvent_t  s_evJoin;
    if (s_sel == nullptr) {
        cudaStreamCreateWithFlags(&s_sel, cudaStreamNonBlocking);
        for (int i = 0; i < BATCH; i++)
            cudaEventCreateWithFlags(&s_evD[i], cudaEventDisableTiming);
        cudaEventCreateWithFlags(&s_evJoin, cudaEventDisableTiming);
        cudaFuncSetAttribute(dist_kernel,
                             cudaFuncAttributeMaxDynamicSharedMemorySize, DIST_SMEM);
    }

    transform_kernel<<<TOTAL / 128, 128>>>(x, W, bias);
    for (int b = 0; b < BATCH; b++) {
        dist_kernel<<<528, 256, DIST_SMEM>>>(x, b);
        cudaEventRecord(s_evD[b], 0);
        cudaStreamWaitEvent(s_sel, s_evD[b], 0);
        select_kernel<<<NPTS, 256, 0, s_sel>>>(b);
    }
    cudaEventRecord(s_evJoin, s_sel);
    cudaStreamWaitEvent(0, s_evJoin, 0);
    gather_kernel<<<(TOTAL * FOUT) / 256, 256>>>(out);
}

// round 10
// speedup vs baseline: 1.7343x; 1.7343x over previous
#include <cuda_runtime.h>
#include <cstdint>

#define BATCH 4
#define NPTS  4096
#define FIN   64
#define FOUT  64
#define KNN   20
#define TOTAL (BATCH * NPTS)   // 16384 points

// ---------------- scratch (static device memory; no allocations) ----------------
__device__ float g_key[(size_t)TOTAL * NPTS];   // 268 MB ranking keys
__device__ float g_xT[BATCH * FIN * NPTS];      // x transposed: [b][f][n]
__device__ float g_u[TOTAL * FOUT];             // (W1-W2)x + b
__device__ float g_v[TOTAL * FOUT];             // W2 x
__device__ float g_xs[TOTAL];                   // squared norms
__device__ int   g_idx[TOTAL * KNN];            // knn indices (local to batch)

// ---------------- kernel A: per-point transform (+ writes transposed x) ----------------
__global__ void transform_kernel(const float* __restrict__ x,
                                 const float* __restrict__ W,
                                 const float* __restrict__ bias) {
    __shared__ float Ws[FOUT * 2 * FIN];
    __shared__ float bs[FOUT];
    int t = threadIdx.x;
    for (int i = t; i < FOUT * 2 * FIN; i += blockDim.x) Ws[i] = W[i];
    if (t < FOUT) bs[t] = bias[t];
    __syncthreads();

    int p = blockIdx.x * blockDim.x + t;
    float xr[FIN];
    const float4* xp = (const float4*)(x + (size_t)p * FIN);
#pragma unroll
    for (int q = 0; q < FIN / 4; q++) {
        float4 v4 = xp[q];
        xr[4*q+0] = v4.x; xr[4*q+1] = v4.y; xr[4*q+2] = v4.z; xr[4*q+3] = v4.w;
    }
    float s = 0.f;
#pragma unroll
    for (int c = 0; c < FIN; c++) s += xr[c] * xr[c];
    g_xs[p] = s;

    // transposed copy: g_xT[b][c][n]; lanes have consecutive p -> coalesced per c
    float* xt = g_xT + (size_t)(p >> 12) * FIN * NPTS + (p & (NPTS - 1));
#pragma unroll
    for (int c = 0; c < FIN; c++) xt[(size_t)c * NPTS] = xr[c];

    for (int o = 0; o < FOUT; o++) {
        float a1 = 0.f, a2 = 0.f;
        const float* wrow = &Ws[o * 2 * FIN];
#pragma unroll
        for (int c = 0; c < FIN; c++) {
            a1 += xr[c] * wrow[c];
            a2 += xr[c] * wrow[FIN + c];
        }
        g_u[p * FOUT + o] = a1 - a2 + bs[o];
        g_v[p * FOUT + o] = a2;
    }
}

// ---------------- kernel B: symmetric Gram + ranking keys ----------------
// f-major smem tiles, stride 132 (mult of 4 -> aligned float4 reads).
// Fill: from g_xT, coalesced LDG.128 + conflict-free STS.128 (bank=4*lane).
// Reads: A broadcast (1 phase), B interleaved cols 4*tc (2-phase floor).
#define TILE 128
#define SSTR 132
#define DIST_SMEM (2 * FIN * SSTR * 4)   // 67584 bytes

__global__ __launch_bounds__(256) void dist_kernel() {
    extern __shared__ float sm[];
    float* At = sm;                 // At[f*SSTR + r], r in [0,128)
    float* Bt = sm + FIN * SSTR;

    int b = blockIdx.z;
    int id = blockIdx.x;            // upper-tri (by,bx), bx >= by
    int by = 0, rem = id;
    while (rem >= 32 - by) { rem -= 32 - by; by++; }
    int bx = by + rem;

    const float* XT = g_xT + (size_t)b * FIN * NPTS;
    int row0 = by * TILE, col0 = bx * TILE;
    int t  = threadIdx.x;
    int tr = t >> 4, tc = t & 15;   // 16x16 threads, 8x8 micro-tile

    // fill f-major tiles: q -> (f, 4-row chunk)
    for (int q = t; q < FIN * 32; q += 256) {
        int f  = q >> 5;
        int rc = (q & 31) * 4;
        *(float4*)&At[f * SSTR + rc] = *(const float4*)(XT + (size_t)f * NPTS + row0 + rc);
        *(float4*)&Bt[f * SSTR + rc] = *(const float4*)(XT + (size_t)f * NPTS + col0 + rc);
    }
    __syncthreads();

    float acc[8][8];
#pragma unroll
    for (int i = 0; i < 8; i++)
#pragma unroll
        for (int j = 0; j < 8; j++) acc[i][j] = 0.f;

    const float* Ar = At + tr * 8;  // rows tr*8 .. +7 (contiguous in f-major)
    const float* Br = Bt + tc * 4;  // cols {4tc..4tc+3} and {64+4tc..}
#pragma unroll 4
    for (int f = 0; f < FIN; f++) {
        float4 a0 = *(const float4*)(Ar + f * SSTR);
        float4 a1 = *(const float4*)(Ar + f * SSTR + 4);
        float4 b0 = *(const float4*)(Br + f * SSTR);
        float4 b1 = *(const float4*)(Br + f * SSTR + 64);
        float av[8] = {a0.x,a0.y,a0.z,a0.w,a1.x,a1.y,a1.z,a1.w};
        float bv[8] = {b0.x,b0.y,b0.z,b0.w,b1.x,b1.y,b1.z,b1.w};
#pragma unroll
        for (int i = 0; i < 8; i++)
#pragma unroll
            for (int j = 0; j < 8; j++)
                acc[i][j] = fmaf(av[i], bv[j], acc[i][j]);
    }

    // global column indices for this thread's interleaved 8 cols
    int colG[8];
#pragma unroll
    for (int j = 0; j < 4; j++) { colG[j] = col0 + tc * 4 + j; colG[j+4] = col0 + 64 + tc * 4 + j; }

    float xsr[8], xsc[8];
#pragma unroll
    for (int i = 0; i < 8; i++) xsr[i] = g_xs[b * NPTS + row0 + tr * 8 + i];
#pragma unroll
    for (int j = 0; j < 8; j++) xsc[j] = g_xs[b * NPTS + colG[j]];

    // direct block: key[row][col] = xs[col] - 2*acc   (two coalesced f4 stores)
#pragma unroll
    for (int i = 0; i < 8; i++) {
        size_t base = (size_t)(b * NPTS + row0 + tr * 8 + i) * NPTS;
        float4 o0 = make_float4(xsc[0] - 2.f*acc[i][0], xsc[1] - 2.f*acc[i][1],
                                xsc[2] - 2.f*acc[i][2], xsc[3] - 2.f*acc[i][3]);
        float4 o1 = make_float4(xsc[4] - 2.f*acc[i][4], xsc[5] - 2.f*acc[i][5],
                                xsc[6] - 2.f*acc[i][6], xsc[7] - 2.f*acc[i][7]);
        __stcs((float4*)&g_key[base + col0 + tc * 4],      o0);
        __stcs((float4*)&g_key[base + col0 + 64 + tc * 4], o1);
    }
    // mirrored block: key[col][row] = xs[row] - 2*acc
    if (bx != by) {
#pragma unroll
        for (int j = 0; j < 8; j++) {
            size_t base = (size_t)(b * NPTS + colG[j]) * NPTS + row0 + tr * 8;
            float4 m0 = make_float4(xsr[0] - 2.f*acc[0][j], xsr[1] - 2.f*acc[1][j],
                                    xsr[2] - 2.f*acc[2][j], xsr[3] - 2.f*acc[3][j]);
            float4 m1 = make_float4(xsr[4] - 2.f*acc[4][j], xsr[5] - 2.f*acc[5][j],
                                    xsr[6] - 2.f*acc[6][j], xsr[7] - 2.f*acc[7][j]);
            __stcs((float4*)&g_key[base],     m0);
            __stcs((float4*)&g_key[base + 4], m1);
        }
    }
}

// ---------------- kernel C: radix top-20 selection ----------------
__global__ __launch_bounds__(256) void select_kernel() {
    int row = blockIdx.x;
    int iLocal = row & (NPTS - 1);
    const float4* keys = (const float4*)(g_key + (size_t)row * NPTS);
    int t = threadIdx.x;

    unsigned v[16];
#pragma unroll
    for (int i2 = 0; i2 < 4; i2++) {
        int f4 = t + i2 * 256;
        float4 kv = __ldcs(&keys[f4]);
        float vv[4] = {kv.x, kv.y, kv.z, kv.w};
        int j0 = f4 * 4;
#pragma unroll
        for (int e = 0; e < 4; e++) {
            unsigned u = __float_as_uint(vv[e]);
            u = (u & 0x80000000u) ? ~u : (u | 0x80000000u);
            v[i2 * 4 + e] = (j0 + e == iLocal) ? 0xFFFFFFFFu : u;
        }
    }

    __shared__ int hist[256];
    __shared__ int sD, sCb, sNeed;
    __shared__ int cnt1, cntT, chosen;
    __shared__ int tieb[64];
    __shared__ int wred[8];

    unsigned prefix = 0, pmask = 0;
    if (t == 0) sNeed = KNN;

    for (int pass = 0; pass < 4; pass++) {
        int shift = 24 - 8 * pass;
        hist[t] = 0;
        __syncthreads();
#pragma unroll
        for (int q = 0; q < 16; q++) {
            bool ok = (v[q] & pmask) == prefix;
            unsigned act = __ballot_sync(0xffffffffu, ok);
            if (ok) {
                unsigned d = (v[q] >> shift) & 255u;
                unsigned m = __match_any_sync(act, d);
                if ((t & 31) == (__ffs(m) - 1))
                    atomicAdd(&hist[d], __popc(m));
            }
        }
        __syncthreads();
        if (t < 32) {
            int s[8], tot = 0, base = t * 8;
#pragma unroll
            for (int q2 = 0; q2 < 8; q2++) { s[q2] = hist[base + q2]; tot += s[q2]; }
            int inc = tot;
#pragma unroll
            for (int off = 1; off < 32; off <<= 1) {
                int o = __shfl_up_sync(0xffffffffu, inc, off);
                if (t >= off) inc += o;
            }
            int ex = inc - tot;
            int nd = sNeed;
            if (ex < nd && nd <= inc) {
                int run = ex;
#pragma unroll
                for (int q2 = 0; q2 < 8; q2++) {
                    if (nd <= run + s[q2]) { sD = base + q2; sCb = run; break; }
                    run += s[q2];
                }
            }
        }
        __syncthreads();
        prefix |= ((unsigned)sD) << shift;
        pmask  |= 0xFFu << shift;
        if (t == 0) sNeed -= sCb;
    }

    if (t == 0) { cnt1 = 0; cntT = 0; }
    __syncthreads();
    unsigned theta = prefix;
    int* outp = g_idx + row * KNN;
#pragma unroll
    for (int q = 0; q < 16; q++) {
        int j = (t + (q >> 2) * 256) * 4 + (q & 3);
        if (v[q] < theta)       { int s2 = atomicAdd(&cnt1, 1); outp[s2] = j; }
        else if (v[q] == theta) { int s2 = atomicAdd(&cntT, 1); if (s2 < 64) tieb[s2] = j; }
    }
    __syncthreads();
    int needF = sNeed;
    if (cntT <= 64) {
        if (t == 0) {
            int c1 = cnt1, nt = cntT;
            for (int s2 = 0; s2 < needF; s2++) {
                int bi = 0, bv = 0x7fffffff;
                for (int q = 0; q < nt; q++) if (tieb[q] < bv) { bv = tieb[q]; bi = q; }
                tieb[bi] = 0x7fffffff;
                outp[c1 + s2] = bv;
            }
        }
    } else {
        unsigned used = 0;
        for (int s2 = 0; s2 < needF; s2++) {
            int lm = 0x7fffffff;
#pragma unroll
            for (int q = 0; q < 16; q++) {
                int j = (t + (q >> 2) * 256) * 4 + (q & 3);
                if (v[q] == theta && !(used & (1u << q)) && j < lm) lm = j;
            }
            int r = lm;
#pragma unroll
            for (int off = 16; off; off >>= 1)
                r = min(r, __shfl_xor_sync(0xffffffffu, r, off));
            if ((t & 31) == 0) wred[t >> 5] = r;
            __syncthreads();
            if (t == 0) {
                int bm = 0x7fffffff;
                for (int w = 0; w < 8; w++) bm = min(bm, wred[w]);
                chosen = bm;
                outp[cnt1 + s2] = bm;
            }
            __syncthreads();
            int cj = chosen;
#pragma unroll
            for (int q = 0; q < 16; q++) {
                int j = (t + (q >> 2) * 256) * 4 + (q & 3);
                if (j == cj) used |= (1u << q);
            }
        }
    }
}

// ---------------- kernel D: gather-max epilogue ----------------
__global__ void gather_kernel(float* __restrict__ out) {
    int gid = blockIdx.x * blockDim.x + threadIdx.x;
    int p = gid >> 6;
    int o = gid & 63;
    int bbase = p & ~(NPTS - 1);
    const int* ip = g_idx + p * KNN;
    float m = -3.402823466e38f;
#pragma unroll
    for (int q = 0; q < KNN; q++) {
        int j = ip[q];
        m = fmaxf(m, g_v[(size_t)(bbase + j) * FOUT + o]);
    }
    out[gid] = g_u[gid] + m;
}

// ---------------- launch: simple single-stream sequence ----------------
extern "C" void kernel_launch(void* const* d_in, const int* in_sizes, int n_in,
                              void* d_out, int out_size) {
    const float* x    = (const float*)d_in[0];
    const float* W    = (const float*)d_in[1];
    const float* bias = (const float*)d_in[2];
    float* out = (float*)d_out;

    static bool s_init = false;
    if (!s_init) {
        s_init = true;
        cudaFuncSetAttribute(dist_kernel,
                             cudaFuncAttributeMaxDynamicSharedMemorySize, DIST_SMEM);
    }

    transform_kernel<<<TOTAL / 128, 128>>>(x, W, bias);
    dist_kernel<<<dim3(528, 1, BATCH), 256, DIST_SMEM>>>();
    select_kernel<<<TOTAL, 256>>>();
    gather_kernel<<<(TOTAL * FOUT) / 256, 256>>>(out);
}